// round 11
// baseline (speedup 1.0000x reference)
#include <cuda_runtime.h>

// PeripheralDWConv2d via hybrid FFT:
//  - pack batch pairs into complex rows (z = x[2k] + i*x[2k+1])
//  - 128-pt register/shuffle DIF FFT along x (table twiddles, bitrev slots)
//  - 51-tap conv along y per frequency slot (transposed smem, y-contig window)
//  - register/shuffle DIT inverse FFT, crop, unpack.

#define KSZ 51
#define PP  13
#define RAD 25
#define NCH 128
#define WROW 52
#define NBIN 128
#define NPIMG 1024          // 8 batch-pairs * 128 channels
#define NPROWS 65536        // NPIMG * 64 y-rows
#define YDIM 64
#define XPAD 114            // 25 zero + 64 data + 25 zero
#define SROW 115            // padded y-stride (odd -> conflict-free)

__device__ float  g_wpad[NCH * KSZ * WROW];
__device__ float2 g_twtab[128];                     // exp(-2*pi*i*k/128)
__device__ float2 g_wf[NCH * KSZ * NBIN];           // conj spectra, bitrev slots
__device__ float2 g_xf[(size_t)NPROWS * NBIN];      // packed row spectra
__device__ float2 g_sf[(size_t)NPROWS * NBIN];      // conv'd spectra

__constant__ int c_qpos[26] = {0,1,2,2,3,3,3,3,4,4,4,4,4,4,4,4,
                               5,5,5,5,5,5,5,5,5,6};

__global__ void build_weights_kernel(const float* __restrict__ wc,
                                     const float* __restrict__ kpe) {
    int t = blockIdx.x * blockDim.x + threadIdx.x;
    const int total = NCH * KSZ * WROW;
    if (t >= total) return;
    int c  = t / (KSZ * WROW);
    int r  = t - c * (KSZ * WROW);
    int dy = r / WROW;
    int dx = r - dy * WROW;
    float v = 0.f;
    if (dx < KSZ) {
        int oi = dy - RAD; int ai = oi < 0 ? -oi : oi;
        int ii = 6 + (oi < 0 ? -c_qpos[ai] : c_qpos[ai]);
        int oj = dx - RAD; int aj = oj < 0 ? -oj : oj;
        int jj = 6 + (oj < 0 ? -c_qpos[aj] : c_qpos[aj]);
        v = wc[c * (PP * PP) + ii * PP + jj] + kpe[dy * KSZ + dx];
    }
    g_wpad[t] = v;
}

__global__ void init_tw_kernel() {
    int k = threadIdx.x;
    if (k < 128) {
        float s, c;
        sincospif(-(float)k / 64.0f, &s, &c);
        g_twtab[k] = make_float2(c, s);
    }
}

__device__ __forceinline__ float2 cmulf(float2 a, float2 b) {
    return make_float2(a.x * b.x - a.y * b.y, a.x * b.y + a.y * b.x);
}
__device__ __forceinline__ float2 cmulc(float2 a, float2 b) {  // a * conj(b)
    return make_float2(a.x * b.x + a.y * b.y, a.y * b.x - a.x * b.y);
}

__device__ __forceinline__ void load_tw(float2 tw[7], int t) {
    tw[0] = g_twtab[t];                // d=64, pair a
    tw[1] = g_twtab[t + 32];           // d=64, pair b
    tw[2] = g_twtab[2 * t];            // d=32
    tw[3] = g_twtab[(t & 15) * 4];     // d=16
    tw[4] = g_twtab[(t & 7) * 8];      // d=8
    tw[5] = g_twtab[(t & 3) * 16];     // d=4
    tw[6] = g_twtab[(t & 1) * 32];     // d=2
}

// Forward 128-pt DIF. Thread t holds elems t,t+32,t+64,t+96.
// Output slot p = bin bitrev7(p).
__device__ __forceinline__ void fft128_fwd(float2 z[4], int t, const float2 tw[7]) {
    {   // d=64
        float2 a, b;
        a = z[0]; b = z[2];
        z[0] = make_float2(a.x + b.x, a.y + b.y);
        z[2] = cmulf(make_float2(a.x - b.x, a.y - b.y), tw[0]);
        a = z[1]; b = z[3];
        z[1] = make_float2(a.x + b.x, a.y + b.y);
        z[3] = cmulf(make_float2(a.x - b.x, a.y - b.y), tw[1]);
    }
    {   // d=32
        float2 a, b;
        a = z[0]; b = z[1];
        z[0] = make_float2(a.x + b.x, a.y + b.y);
        z[1] = cmulf(make_float2(a.x - b.x, a.y - b.y), tw[2]);
        a = z[2]; b = z[3];
        z[2] = make_float2(a.x + b.x, a.y + b.y);
        z[3] = cmulf(make_float2(a.x - b.x, a.y - b.y), tw[2]);
    }
#pragma unroll
    for (int s = 0; s < 5; ++s) {      // d = 16,8,4,2,1
        int d = 16 >> s;
        float2 w = (s < 4) ? tw[3 + s] : make_float2(1.f, 0.f);
        bool hi = (t & d) != 0;
#pragma unroll
        for (int j = 0; j < 4; ++j) {
            float ox = __shfl_xor_sync(0xffffffffu, z[j].x, d);
            float oy = __shfl_xor_sync(0xffffffffu, z[j].y, d);
            if (hi) {
                float2 df = make_float2(ox - z[j].x, oy - z[j].y);
                z[j] = (d == 1) ? df : cmulf(df, w);
            } else {
                z[j] = make_float2(z[j].x + ox, z[j].y + oy);
            }
        }
    }
}

// Inverse 128-pt DIT (unnormalized). Input slot p = bin bitrev7(p); natural out.
__device__ __forceinline__ void fft128_inv(float2 z[4], int t, const float2 tw[7]) {
#pragma unroll
    for (int s = 0; s < 5; ++s) {      // d = 1,2,4,8,16
        int d = 1 << s;
        float2 w = (s > 0) ? tw[7 - s] : make_float2(1.f, 0.f);  // tw[6..3]
        bool hi = (t & d) != 0;
#pragma unroll
        for (int j = 0; j < 4; ++j) {
            float ox = __shfl_xor_sync(0xffffffffu, z[j].x, d);
            float oy = __shfl_xor_sync(0xffffffffu, z[j].y, d);
            if (hi) {
                float2 vm = (d == 1) ? z[j] : cmulc(z[j], w);
                z[j] = make_float2(ox - vm.x, oy - vm.y);
            } else {
                float2 vo = (d == 1) ? make_float2(ox, oy)
                                     : cmulc(make_float2(ox, oy), w);
                z[j] = make_float2(z[j].x + vo.x, z[j].y + vo.y);
            }
        }
    }
    {   // len=64 local: w = conj(tw[2])
        float2 u, v;
        v = cmulc(z[1], tw[2]); u = z[0];
        z[0] = make_float2(u.x + v.x, u.y + v.y);
        z[1] = make_float2(u.x - v.x, u.y - v.y);
        v = cmulc(z[3], tw[2]); u = z[2];
        z[2] = make_float2(u.x + v.x, u.y + v.y);
        z[3] = make_float2(u.x - v.x, u.y - v.y);
    }
    {   // len=128 local: conj(tw[0]), conj(tw[1])
        float2 u, v;
        v = cmulc(z[2], tw[0]); u = z[0];
        z[0] = make_float2(u.x + v.x, u.y + v.y);
        z[2] = make_float2(u.x - v.x, u.y - v.y);
        v = cmulc(z[3], tw[1]); u = z[1];
        z[1] = make_float2(u.x + v.x, u.y + v.y);
        z[3] = make_float2(u.x - v.x, u.y - v.y);
    }
}

__global__ __launch_bounds__(256) void fft_w_kernel() {
    int t = threadIdx.x & 31, w = threadIdx.x >> 5;
    float2 tw[7]; load_tw(tw, t);
    int row = blockIdx.x * 8 + w;                 // c*51+dy, < 6528
    const float* src = g_wpad + row * WROW;
    float2 z[4];
    z[0] = make_float2(src[t], 0.f);
    z[1] = make_float2((t + 32) < KSZ ? src[t + 32] : 0.f, 0.f);
    z[2] = make_float2(0.f, 0.f);
    z[3] = make_float2(0.f, 0.f);
    fft128_fwd(z, t, tw);
    float2* dst = g_wf + (size_t)row * NBIN;
    dst[t]      = make_float2(z[0].x, -z[0].y);
    dst[t + 32] = make_float2(z[1].x, -z[1].y);
    dst[t + 64] = make_float2(z[2].x, -z[2].y);
    dst[t + 96] = make_float2(z[3].x, -z[3].y);
}

__global__ __launch_bounds__(256) void fft_x_kernel(const float* __restrict__ x) {
    int t = threadIdx.x & 31, w = threadIdx.x >> 5;
    float2 tw[7]; load_tw(tw, t);
    int row = blockIdx.x * 8 + w;                 // < 65536
    int pimg = row >> 6;
    int y    = row & 63;
    int pb   = pimg >> 7;
    int c    = pimg & 127;
    const float* r0 = x + (((size_t)(2 * pb)     * NCH + c) * 64 + y) * 64;
    const float* r1 = x + (((size_t)(2 * pb + 1) * NCH + c) * 64 + y) * 64;
    float2 z[4];
    z[0] = make_float2(r0[t],      r1[t]);
    z[1] = make_float2(r0[t + 32], r1[t + 32]);
    z[2] = make_float2(0.f, 0.f);
    z[3] = make_float2(0.f, 0.f);
    fft128_fwd(z, t, tw);
    float2* dst = g_xf + (size_t)row * NBIN;
    dst[t]      = z[0];
    dst[t + 32] = z[1];
    dst[t + 64] = z[2];
    dst[t + 96] = z[3];
}

// 51-tap conv along y per frequency slot. CTA = (packed image, 64-bin half).
// Transposed smem [f][s] split re/im; thread = (bin f, 16 consecutive y).
__global__ __launch_bounds__(256, 2) void yconv_kernel() {
    extern __shared__ float smf[];
    float* Xr = smf;                       // 64 * SROW
    float* Xi = Xr + 64 * SROW;            // 64 * SROW
    float* Wr = Xi + 64 * SROW;            // 51 * 64
    float* Wi = Wr + KSZ * 64;             // 51 * 64
    const int pimg = blockIdx.x >> 1;
    const int binb = (blockIdx.x & 1) * 64;
    const int c    = pimg & (NCH - 1);
    const int tid  = threadIdx.x;

    {   // weights: [dy][f] split planes (conflict-free: lanes consecutive f)
        const float2* wsrc = g_wf + (size_t)c * (KSZ * NBIN) + binb;
        for (int i = tid; i < KSZ * 64; i += 256) {
            int dy = i >> 6, f = i & 63;
            float2 v = wsrc[dy * NBIN + f];
            Wr[i] = v.x;
            Wi[i] = v.y;
        }
    }
    {   // transpose fill: gmem [y][bin] -> smem [f][s], s = y + 25
        const float2* xsrc = g_xf + (size_t)pimg * (YDIM * NBIN) + binb;
        for (int i = tid; i < XPAD * 64; i += 256) {
            int s = i >> 6, f = i & 63;
            int ys = s - RAD;
            float2 v = make_float2(0.f, 0.f);
            if ((unsigned)ys < (unsigned)YDIM) v = xsrc[(size_t)ys * NBIN + f];
            Xr[f * SROW + s] = v.x;     // lanes: stride SROW (odd) -> no conflict
            Xi[f * SROW + s] = v.y;
        }
    }
    __syncthreads();

    const int f  = tid & 63;
    const int yb = tid >> 6;               // 0..3
    const int y0 = yb * 16;
    const float* xr = Xr + f * SROW + y0;
    const float* xi = Xi + f * SROW + y0;
    const float* wr = Wr + f;
    const float* wi = Wi + f;

    float ar[16], ai[16], win_r[16], win_i[16];
#pragma unroll
    for (int i = 0; i < 16; ++i) { ar[i] = 0.f; ai[i] = 0.f; }
#pragma unroll
    for (int j = 0; j < 15; ++j) { win_r[j] = xr[j]; win_i[j] = xi[j]; }

#pragma unroll
    for (int dy = 0; dy < KSZ; ++dy) {
        win_r[(dy + 15) & 15] = xr[dy + 15];   // s = y0+dy+15 <= 113, in-bounds
        win_i[(dy + 15) & 15] = xi[dy + 15];
        float wvr = wr[dy * 64];
        float wvi = wi[dy * 64];
#pragma unroll
        for (int i = 0; i < 16; ++i) {
            float xrv = win_r[(dy + i) & 15];
            float xiv = win_i[(dy + i) & 15];
            ar[i] = fmaf(xrv, wvr, fmaf(-xiv, wvi, ar[i]));
            ai[i] = fmaf(xrv, wvi, fmaf( xiv, wvr, ai[i]));
        }
    }

    float2* dst = g_sf + (size_t)pimg * (YDIM * NBIN) + binb;
#pragma unroll
    for (int i = 0; i < 16; ++i)
        dst[(size_t)(y0 + i) * NBIN + f] = make_float2(ar[i], ai[i]);
}

__global__ __launch_bounds__(256) void ifft_kernel(float* __restrict__ out) {
    int t = threadIdx.x & 31, w = threadIdx.x >> 5;
    float2 tw[7]; load_tw(tw, t);
    int row = blockIdx.x * 8 + w;                 // < 65536
    const float2* S = g_sf + (size_t)row * NBIN;
    float2 z[4];
    z[0] = S[t];
    z[1] = S[t + 32];
    z[2] = S[t + 64];
    z[3] = S[t + 96];
    fft128_inv(z, t, tw);

    int pimg = row >> 6, y = row & 63;
    int pb = pimg >> 7, c = pimg & 127;
    float* o0 = out + (((size_t)(2 * pb)     * NCH + c) * 64 + y) * 64;
    float* o1 = out + (((size_t)(2 * pb + 1) * NCH + c) * 64 + y) * 64;
    const float s = 1.0f / 128.0f;
    o0[t + 25] = z[0].x * s;
    o1[t + 25] = z[0].y * s;
    if (t < 7) {
        o0[t + 57] = z[1].x * s;
        o1[t + 57] = z[1].y * s;
    } else {
        o0[t - 7] = z[3].x * s;
        o1[t - 7] = z[3].y * s;
    }
}

extern "C" void kernel_launch(void* const* d_in, const int* in_sizes, int n_in,
                              void* d_out, int out_size) {
    const float* x   = (const float*)d_in[0];   // 16*128*64*64
    const float* wc  = (const float*)d_in[1];   // 128*169
    const float* kpe = (const float*)d_in[2];   // 51*51
    float* out = (float*)d_out;

    init_tw_kernel<<<1, 128>>>();

    const int total_w = NCH * KSZ * WROW;
    build_weights_kernel<<<(total_w + 255) / 256, 256>>>(wc, kpe);

    fft_w_kernel<<<(NCH * KSZ) / 8, 256>>>();        // 6528 rows
    fft_x_kernel<<<NPROWS / 8, 256>>>(x);            // 65536 packed rows

    const size_t ysmem =
        (size_t)(2 * 64 * SROW + 2 * KSZ * 64) * sizeof(float);   // 84992 B
    cudaFuncSetAttribute(yconv_kernel,
                         cudaFuncAttributeMaxDynamicSharedMemorySize, (int)ysmem);
    yconv_kernel<<<NPIMG * 2, 256, ysmem>>>();

    ifft_kernel<<<NPROWS / 8, 256>>>(out);
}

// round 12
// speedup vs baseline: 1.2941x; 1.2941x over previous
#include <cuda_runtime.h>

// PeripheralDWConv2d, fully fused FFT kernel:
//  one CTA per packed image (z = x[2k] + i*x[2k+1]):
//   1. 128-pt register/shuffle DIF FFT along x for 64 rows -> transposed
//      smem planes Xr/Xi[f][s] (s = y+25, zero halo)
//   2. 51-tap conv along y per frequency slot (weights staged in smem)
//   3. register/shuffle DIT inverse FFT per row, crop, unpack, store.

#define KSZ 51
#define PP  13
#define RAD 25
#define NCH 128
#define WROW 52
#define NBIN 128
#define NPIMG 1024          // 8 batch-pairs * 128 channels
#define YDIM 64
#define SROW 115            // padded y-stride (odd -> conflict-free)

__device__ float  g_wpad[NCH * KSZ * WROW];
__device__ float2 g_twtab[128];                     // exp(-2*pi*i*k/128)
__device__ float2 g_wf[NCH * KSZ * NBIN];           // conj spectra, bitrev slots

__constant__ int c_qpos[26] = {0,1,2,2,3,3,3,3,4,4,4,4,4,4,4,4,
                               5,5,5,5,5,5,5,5,5,6};

__global__ void build_weights_kernel(const float* __restrict__ wc,
                                     const float* __restrict__ kpe) {
    int t = blockIdx.x * blockDim.x + threadIdx.x;
    const int total = NCH * KSZ * WROW;
    if (t >= total) return;
    int c  = t / (KSZ * WROW);
    int r  = t - c * (KSZ * WROW);
    int dy = r / WROW;
    int dx = r - dy * WROW;
    float v = 0.f;
    if (dx < KSZ) {
        int oi = dy - RAD; int ai = oi < 0 ? -oi : oi;
        int ii = 6 + (oi < 0 ? -c_qpos[ai] : c_qpos[ai]);
        int oj = dx - RAD; int aj = oj < 0 ? -oj : oj;
        int jj = 6 + (oj < 0 ? -c_qpos[aj] : c_qpos[aj]);
        v = wc[c * (PP * PP) + ii * PP + jj] + kpe[dy * KSZ + dx];
    }
    g_wpad[t] = v;
}

__global__ void init_tw_kernel() {
    int k = threadIdx.x;
    if (k < 128) {
        float s, c;
        sincospif(-(float)k / 64.0f, &s, &c);
        g_twtab[k] = make_float2(c, s);
    }
}

__device__ __forceinline__ float2 cmulf(float2 a, float2 b) {
    return make_float2(a.x * b.x - a.y * b.y, a.x * b.y + a.y * b.x);
}
__device__ __forceinline__ float2 cmulc(float2 a, float2 b) {  // a * conj(b)
    return make_float2(a.x * b.x + a.y * b.y, a.y * b.x - a.x * b.y);
}

__device__ __forceinline__ void load_tw(float2 tw[7], int t) {
    tw[0] = g_twtab[t];                // d=64, pair a
    tw[1] = g_twtab[t + 32];           // d=64, pair b
    tw[2] = g_twtab[2 * t];            // d=32
    tw[3] = g_twtab[(t & 15) * 4];     // d=16
    tw[4] = g_twtab[(t & 7) * 8];      // d=8
    tw[5] = g_twtab[(t & 3) * 16];     // d=4
    tw[6] = g_twtab[(t & 1) * 32];     // d=2
}

// Forward 128-pt DIF. Thread t holds elems t,t+32,t+64,t+96.
// Output slot p = bin bitrev7(p).
__device__ __forceinline__ void fft128_fwd(float2 z[4], int t, const float2 tw[7]) {
    {   // d=64
        float2 a, b;
        a = z[0]; b = z[2];
        z[0] = make_float2(a.x + b.x, a.y + b.y);
        z[2] = cmulf(make_float2(a.x - b.x, a.y - b.y), tw[0]);
        a = z[1]; b = z[3];
        z[1] = make_float2(a.x + b.x, a.y + b.y);
        z[3] = cmulf(make_float2(a.x - b.x, a.y - b.y), tw[1]);
    }
    {   // d=32
        float2 a, b;
        a = z[0]; b = z[1];
        z[0] = make_float2(a.x + b.x, a.y + b.y);
        z[1] = cmulf(make_float2(a.x - b.x, a.y - b.y), tw[2]);
        a = z[2]; b = z[3];
        z[2] = make_float2(a.x + b.x, a.y + b.y);
        z[3] = cmulf(make_float2(a.x - b.x, a.y - b.y), tw[2]);
    }
#pragma unroll
    for (int s = 0; s < 5; ++s) {      // d = 16,8,4,2,1
        int d = 16 >> s;
        float2 w = (s < 4) ? tw[3 + s] : make_float2(1.f, 0.f);
        bool hi = (t & d) != 0;
#pragma unroll
        for (int j = 0; j < 4; ++j) {
            float ox = __shfl_xor_sync(0xffffffffu, z[j].x, d);
            float oy = __shfl_xor_sync(0xffffffffu, z[j].y, d);
            if (hi) {
                float2 df = make_float2(ox - z[j].x, oy - z[j].y);
                z[j] = (d == 1) ? df : cmulf(df, w);
            } else {
                z[j] = make_float2(z[j].x + ox, z[j].y + oy);
            }
        }
    }
}

// Inverse 128-pt DIT (unnormalized). Input slot p = bin bitrev7(p); natural out.
__device__ __forceinline__ void fft128_inv(float2 z[4], int t, const float2 tw[7]) {
#pragma unroll
    for (int s = 0; s < 5; ++s) {      // d = 1,2,4,8,16
        int d = 1 << s;
        float2 w = (s > 0) ? tw[7 - s] : make_float2(1.f, 0.f);  // tw[6..3]
        bool hi = (t & d) != 0;
#pragma unroll
        for (int j = 0; j < 4; ++j) {
            float ox = __shfl_xor_sync(0xffffffffu, z[j].x, d);
            float oy = __shfl_xor_sync(0xffffffffu, z[j].y, d);
            if (hi) {
                float2 vm = (d == 1) ? z[j] : cmulc(z[j], w);
                z[j] = make_float2(ox - vm.x, oy - vm.y);
            } else {
                float2 vo = (d == 1) ? make_float2(ox, oy)
                                     : cmulc(make_float2(ox, oy), w);
                z[j] = make_float2(z[j].x + vo.x, z[j].y + vo.y);
            }
        }
    }
    {   // len=64 local: w = conj(tw[2])
        float2 u, v;
        v = cmulc(z[1], tw[2]); u = z[0];
        z[0] = make_float2(u.x + v.x, u.y + v.y);
        z[1] = make_float2(u.x - v.x, u.y - v.y);
        v = cmulc(z[3], tw[2]); u = z[2];
        z[2] = make_float2(u.x + v.x, u.y + v.y);
        z[3] = make_float2(u.x - v.x, u.y - v.y);
    }
    {   // len=128 local: conj(tw[0]), conj(tw[1])
        float2 u, v;
        v = cmulc(z[2], tw[0]); u = z[0];
        z[0] = make_float2(u.x + v.x, u.y + v.y);
        z[2] = make_float2(u.x - v.x, u.y - v.y);
        v = cmulc(z[3], tw[1]); u = z[1];
        z[1] = make_float2(u.x + v.x, u.y + v.y);
        z[3] = make_float2(u.x - v.x, u.y - v.y);
    }
}

__global__ __launch_bounds__(256) void fft_w_kernel() {
    int t = threadIdx.x & 31, w = threadIdx.x >> 5;
    float2 tw[7]; load_tw(tw, t);
    int row = blockIdx.x * 8 + w;                 // c*51+dy, < 6528
    const float* src = g_wpad + row * WROW;
    float2 z[4];
    z[0] = make_float2(src[t], 0.f);
    z[1] = make_float2((t + 32) < KSZ ? src[t + 32] : 0.f, 0.f);
    z[2] = make_float2(0.f, 0.f);
    z[3] = make_float2(0.f, 0.f);
    fft128_fwd(z, t, tw);
    float2* dst = g_wf + (size_t)row * NBIN;
    dst[t]      = make_float2(z[0].x, -z[0].y);
    dst[t + 32] = make_float2(z[1].x, -z[1].y);
    dst[t + 64] = make_float2(z[2].x, -z[2].y);
    dst[t + 96] = make_float2(z[3].x, -z[3].y);
}

// Fully fused: fwd FFT -> transposed smem -> y-conv -> inverse FFT -> out.
// One CTA per packed image, 512 threads.
__global__ __launch_bounds__(512, 1)
void conv_mono_kernel(const float* __restrict__ x, float* __restrict__ out) {
    extern __shared__ float smf[];
    float*  Xr = smf;                        // 128 * SROW
    float*  Xi = Xr + NBIN * SROW;           // 128 * SROW
    float2* WS = (float2*)(Xi + NBIN * SROW); // 64*128 float2: weights, then S

    const int pimg = blockIdx.x;
    const int pb   = pimg >> 7;
    const int c    = pimg & 127;
    const int tid  = threadIdx.x;
    const int t    = tid & 31;               // lane
    const int w    = tid >> 5;               // warp 0..15

    float2 tw[7]; load_tw(tw, t);

    // phase 0: zero spectra planes + stage weights into WS
    for (int i = tid; i < NBIN * SROW; i += 512) { Xr[i] = 0.f; Xi[i] = 0.f; }
    {
        const float2* wsrc = g_wf + (size_t)c * (KSZ * NBIN);
        for (int i = tid; i < KSZ * NBIN; i += 512) WS[i] = wsrc[i];
    }
    __syncthreads();

    // phase 1: fwd FFT 4 rows per warp, scatter to transposed planes
    const float* img0 = x + (((size_t)(2 * pb)     * NCH + c) * 64) * 64;
    const float* img1 = x + (((size_t)(2 * pb + 1) * NCH + c) * 64) * 64;
#pragma unroll
    for (int r = 0; r < 4; ++r) {
        int y = w * 4 + r;                    // 0..63
        const float* r0 = img0 + y * 64;
        const float* r1 = img1 + y * 64;
        float2 z[4];
        z[0] = make_float2(r0[t],      r1[t]);
        z[1] = make_float2(r0[t + 32], r1[t + 32]);
        z[2] = make_float2(0.f, 0.f);
        z[3] = make_float2(0.f, 0.f);
        fft128_fwd(z, t, tw);
        int s = y + RAD;
#pragma unroll
        for (int j = 0; j < 4; ++j) {
            Xr[(t + 32 * j) * SROW + s] = z[j].x;
            Xi[(t + 32 * j) * SROW + s] = z[j].y;
        }
    }
    __syncthreads();

    // phase 2: y-conv. task = (bin f, 16-consecutive-y block)
    const int f  = tid & 127;
    const int y0 = (tid >> 7) * 16;           // 0,16,32,48
    float ar[16], ai[16];
    {
        const float*  xr = Xr + f * SROW + y0;
        const float*  xi = Xi + f * SROW + y0;
        const float2* wp = WS + f;

        float win_r[16], win_i[16];
#pragma unroll
        for (int i = 0; i < 16; ++i) { ar[i] = 0.f; ai[i] = 0.f; }
#pragma unroll
        for (int j = 0; j < 15; ++j) { win_r[j] = xr[j]; win_i[j] = xi[j]; }

#pragma unroll
        for (int dy = 0; dy < KSZ; ++dy) {
            win_r[(dy + 15) & 15] = xr[dy + 15];   // max s = 48+65 = 113 < 115
            win_i[(dy + 15) & 15] = xi[dy + 15];
            float2 wv = wp[dy * NBIN];
#pragma unroll
            for (int i = 0; i < 16; ++i) {
                float xrv = win_r[(dy + i) & 15];
                float xiv = win_i[(dy + i) & 15];
                ar[i] = fmaf(xrv, wv.x, fmaf(-xiv, wv.y, ar[i]));
                ai[i] = fmaf(xrv, wv.y, fmaf( xiv, wv.x, ai[i]));
            }
        }
    }
    __syncthreads();   // all weight reads done; WS becomes S

    // phase 3: store S[y][f]
#pragma unroll
    for (int i = 0; i < 16; ++i)
        WS[(y0 + i) * NBIN + f] = make_float2(ar[i], ai[i]);
    __syncthreads();

    // phase 4: inverse FFT 4 rows per warp, crop, unpack, write out
    float* o0 = out + (((size_t)(2 * pb)     * NCH + c) * 64) * 64;
    float* o1 = out + (((size_t)(2 * pb + 1) * NCH + c) * 64) * 64;
    const float scl = 1.0f / 128.0f;
#pragma unroll
    for (int r = 0; r < 4; ++r) {
        int y = w * 4 + r;
        const float2* S = WS + y * NBIN;
        float2 z[4];
        z[0] = S[t];
        z[1] = S[t + 32];
        z[2] = S[t + 64];
        z[3] = S[t + 96];
        fft128_inv(z, t, tw);
        float* p0 = o0 + y * 64;
        float* p1 = o1 + y * 64;
        p0[t + 25] = z[0].x * scl;
        p1[t + 25] = z[0].y * scl;
        if (t < 7) {
            p0[t + 57] = z[1].x * scl;
            p1[t + 57] = z[1].y * scl;
        } else {
            p0[t - 7] = z[3].x * scl;
            p1[t - 7] = z[3].y * scl;
        }
    }
}

extern "C" void kernel_launch(void* const* d_in, const int* in_sizes, int n_in,
                              void* d_out, int out_size) {
    const float* x   = (const float*)d_in[0];   // 16*128*64*64
    const float* wc  = (const float*)d_in[1];   // 128*169
    const float* kpe = (const float*)d_in[2];   // 51*51
    float* out = (float*)d_out;

    init_tw_kernel<<<1, 128>>>();

    const int total_w = NCH * KSZ * WROW;
    build_weights_kernel<<<(total_w + 255) / 256, 256>>>(wc, kpe);

    fft_w_kernel<<<(NCH * KSZ) / 8, 256>>>();        // 6528 rows

    const size_t msmem = (size_t)(2 * NBIN * SROW) * sizeof(float)
                       + (size_t)(YDIM * NBIN) * sizeof(float2);   // 183296 B
    cudaFuncSetAttribute(conv_mono_kernel,
                         cudaFuncAttributeMaxDynamicSharedMemorySize, (int)msmem);
    conv_mono_kernel<<<NPIMG, 512, msmem>>>(x, out);
}